// round 2
// baseline (speedup 1.0000x reference)
#include <cuda_runtime.h>

#define OBS_D 128
#define HID_D 256
#define ACT_D 32
#define NPOL 64
#define NBATCH 4096
#define BT 64           // batch-tile rows per CTA
#define KC 32           // K chunk for weight streaming
#define SSTR (HID_D + 4)  // 260, padded smem row stride (floats)
#define NTHREADS 512

typedef unsigned long long ull;

__device__ __forceinline__ ull pack2(float v) {
    ull r;
    asm("mov.b64 %0, {%1, %1};" : "=l"(r) : "f"(v));
    return r;
}
__device__ __forceinline__ void fma2(ull& d, ull a, ull b) {
    asm("fma.rn.f32x2 %0, %1, %2, %3;" : "=l"(d) : "l"(a), "l"(b), "l"(d));
}
__device__ __forceinline__ float2 unpack2(ull v) {
    float2 r;
    asm("mov.b64 {%0, %1}, %2;" : "=f"(r.x), "=f"(r.y) : "l"(v));
    return r;
}

// One hidden layer: sOut[64, 256] = GN(ELU?)(sIn[64, DIN] @ W[DIN,256] + b)
// 512 threads: tx = tid&31 (column pairs), ty = tid>>5 (row groups of 4).
template<int DIN, bool DOACT>
__device__ __forceinline__ void layer_hid(
    int tid,
    const float* __restrict__ Wp, const float* __restrict__ bp,
    const float* __restrict__ gp, const float* __restrict__ bep,
    const float* sIn, float* sOut, float* sW,
    float* sBias, float* sG, float* sBe)
{
    const int tx = tid & 31;
    const int ty = tid >> 5;   // 0..15 -> rows ty*4 .. ty*4+3

    if (tid < HID_D) {
        sBias[tid] = bp[tid];
        sG[tid]    = gp[tid];
        sBe[tid]   = bep[tid];
    }

    ull acc[4][4];
#pragma unroll
    for (int r = 0; r < 4; r++)
#pragma unroll
        for (int j = 0; j < 4; j++) acc[r][j] = 0ull;

    for (int kb = 0; kb < DIN; kb += KC) {
        __syncthreads();   // prior consumers of sW / producers of sIn done
        // cooperative load of W chunk [KC, 256] = 2048 float4
        {
            const float4* wsrc = (const float4*)(Wp + (size_t)kb * HID_D);
            float4* wdst = (float4*)sW;
#pragma unroll
            for (int i = 0; i < (KC * HID_D / 4) / NTHREADS; i++)
                wdst[tid + i * NTHREADS] = wsrc[tid + i * NTHREADS];
        }
        __syncthreads();
#pragma unroll
        for (int k = 0; k < KC; k++) {
            ull a[4];
#pragma unroll
            for (int r = 0; r < 4; r++)
                a[r] = pack2(sIn[(ty * 4 + r) * SSTR + kb + k]);
#pragma unroll
            for (int j = 0; j < 4; j++) {
                ull w = *(const ull*)(sW + k * HID_D + j * 64 + tx * 2);
#pragma unroll
                for (int r = 0; r < 4; r++) fma2(acc[r][j], a[r], w);
            }
        }
    }

    // bias add + store raw y to sOut
#pragma unroll
    for (int r = 0; r < 4; r++) {
#pragma unroll
        for (int j = 0; j < 4; j++) {
            int c = j * 64 + tx * 2;
            float2 v = unpack2(acc[r][j]);
            v.x += sBias[c];
            v.y += sBias[c + 1];
            *(float2*)(sOut + (ty * 4 + r) * SSTR + c) = v;
        }
    }
    __syncthreads();

    // GroupNorm over 256 per row + optional ELU, in place. 8 threads/row.
    {
        const int row = tid >> 3;
        const int sub = tid & 7;
        float* prow = sOut + row * SSTR;
        float s = 0.f, s2 = 0.f;
#pragma unroll
        for (int j = 0; j < HID_D / 8; j++) {
            float v = prow[j * 8 + sub];
            s += v; s2 += v * v;
        }
        s  += __shfl_xor_sync(0xffffffffu, s, 1);
        s2 += __shfl_xor_sync(0xffffffffu, s2, 1);
        s  += __shfl_xor_sync(0xffffffffu, s, 2);
        s2 += __shfl_xor_sync(0xffffffffu, s2, 2);
        s  += __shfl_xor_sync(0xffffffffu, s, 4);
        s2 += __shfl_xor_sync(0xffffffffu, s2, 4);
        float mu   = s * (1.f / HID_D);
        float var  = fmaxf(s2 * (1.f / HID_D) - mu * mu, 0.f);
        float rstd = rsqrtf(var + 1e-5f);
#pragma unroll
        for (int j = 0; j < HID_D / 8; j++) {
            int c = j * 8 + sub;
            float v = (prow[c] - mu) * rstd * sG[c] + sBe[c];
            if (DOACT) v = (v > 0.f) ? v : expm1f(v);
            prow[c] = v;
        }
    }
    __syncthreads();
}

// Final layer: out[64, 32] = GN(sIn[64,256] @ W4[256,32] + b4), no activation.
// 512 threads: row = tid>>3 (64 rows), sub = tid&7 (4 cols each as 2 pairs).
__device__ __forceinline__ void layer_out(
    int tid, int p, int b0,
    const float* __restrict__ Wp, const float* __restrict__ bp,
    const float* __restrict__ gp, const float* __restrict__ bep,
    const float* sIn, float* sW,
    float* sBias, float* sG, float* sBe,
    float* __restrict__ out)
{
    if (tid < ACT_D) {
        sBias[tid] = bp[tid];
        sG[tid]    = gp[tid];
        sBe[tid]   = bep[tid];
    }
    const int row = tid >> 3;
    const int sub = tid & 7;

    ull acc0 = 0ull, acc1 = 0ull;
    for (int kb = 0; kb < HID_D; kb += KC) {
        __syncthreads();
        if (tid < (KC * ACT_D / 4))   // 256 float4
            ((float4*)sW)[tid] = ((const float4*)(Wp + (size_t)kb * ACT_D))[tid];
        __syncthreads();
#pragma unroll
        for (int k = 0; k < KC; k++) {
            ull a = pack2(sIn[row * SSTR + kb + k]);
            fma2(acc0, a, *(const ull*)(sW + k * ACT_D + sub * 4));
            fma2(acc1, a, *(const ull*)(sW + k * ACT_D + sub * 4 + 2));
        }
    }

    float2 v0 = unpack2(acc0), v1 = unpack2(acc1);
    const int c0 = sub * 4;
    v0.x += sBias[c0];     v0.y += sBias[c0 + 1];
    v1.x += sBias[c0 + 2]; v1.y += sBias[c0 + 3];

    float s  = v0.x + v0.y + v1.x + v1.y;
    float s2 = v0.x * v0.x + v0.y * v0.y + v1.x * v1.x + v1.y * v1.y;
    s  += __shfl_xor_sync(0xffffffffu, s, 1);
    s2 += __shfl_xor_sync(0xffffffffu, s2, 1);
    s  += __shfl_xor_sync(0xffffffffu, s, 2);
    s2 += __shfl_xor_sync(0xffffffffu, s2, 2);
    s  += __shfl_xor_sync(0xffffffffu, s, 4);
    s2 += __shfl_xor_sync(0xffffffffu, s2, 4);
    float mu   = s * (1.f / ACT_D);
    float var  = fmaxf(s2 * (1.f / ACT_D) - mu * mu, 0.f);
    float rstd = rsqrtf(var + 1e-5f);

    float2 o0, o1;
    o0.x = (v0.x - mu) * rstd * sG[c0]     + sBe[c0];
    o0.y = (v0.y - mu) * rstd * sG[c0 + 1] + sBe[c0 + 1];
    o1.x = (v1.x - mu) * rstd * sG[c0 + 2] + sBe[c0 + 2];
    o1.y = (v1.y - mu) * rstd * sG[c0 + 3] + sBe[c0 + 3];

    float* orow = out + (size_t)(b0 + row) * (NPOL * ACT_D) + (size_t)p * ACT_D;
    *(float2*)(orow + c0)     = o0;
    *(float2*)(orow + c0 + 2) = o1;
}

__global__ void __launch_bounds__(NTHREADS, 1)
mlp_fused_kernel(
    const float* __restrict__ obs,
    const float* __restrict__ W1, const float* __restrict__ b1,
    const float* __restrict__ g1, const float* __restrict__ be1,
    const float* __restrict__ W2, const float* __restrict__ b2,
    const float* __restrict__ g2, const float* __restrict__ be2,
    const float* __restrict__ W3, const float* __restrict__ b3,
    const float* __restrict__ g3, const float* __restrict__ be3,
    const float* __restrict__ W4, const float* __restrict__ b4,
    const float* __restrict__ g4, const float* __restrict__ be4,
    float* __restrict__ out)
{
    extern __shared__ float smem[];
    float* sA    = smem;                    // BT * SSTR
    float* sB    = sA + BT * SSTR;          // BT * SSTR
    float* sW    = sB + BT * SSTR;          // KC * HID_D
    float* sBias = sW + KC * HID_D;         // HID_D
    float* sG    = sBias + HID_D;           // HID_D
    float* sBe   = sG + HID_D;              // HID_D

    const int tid = threadIdx.x;
    const int p   = blockIdx.y;
    const int b0  = blockIdx.x * BT;

    // Load observation tile [BT, 128] into sA (broadcast across policies).
    {
        const float4* src = (const float4*)(obs + (size_t)b0 * OBS_D);
#pragma unroll
        for (int i = 0; i < (BT * OBS_D / 4) / NTHREADS; i++) {  // 4 iters
            int idx = tid + i * NTHREADS;
            int row = idx >> 5;        // OBS_D/4 = 32 float4 per row
            int c4  = idx & 31;
            // row*SSTR floats = row*1040 bytes, 16B aligned (1040 = 65*16)
            ((float4*)(sA + row * SSTR))[c4] = src[idx];
        }
    }
    // (visibility guaranteed by the __syncthreads at top of first K-chunk)

    const size_t pO = (size_t)p;
    layer_hid<OBS_D, true >(tid, W1 + pO * OBS_D * HID_D, b1 + pO * HID_D,
                            g1 + pO * HID_D, be1 + pO * HID_D,
                            sA, sB, sW, sBias, sG, sBe);
    layer_hid<HID_D, true >(tid, W2 + pO * HID_D * HID_D, b2 + pO * HID_D,
                            g2 + pO * HID_D, be2 + pO * HID_D,
                            sB, sA, sW, sBias, sG, sBe);
    layer_hid<HID_D, true >(tid, W3 + pO * HID_D * HID_D, b3 + pO * HID_D,
                            g3 + pO * HID_D, be3 + pO * HID_D,
                            sA, sB, sW, sBias, sG, sBe);
    layer_out(tid, p, b0, W4 + pO * HID_D * ACT_D, b4 + pO * ACT_D,
              g4 + pO * ACT_D, be4 + pO * ACT_D,
              sB, sW, sBias, sG, sBe, out);
}

extern "C" void kernel_launch(void* const* d_in, const int* in_sizes, int n_in,
                              void* d_out, int out_size)
{
    const float* obs = (const float*)d_in[0];
    const float* W1  = (const float*)d_in[1];
    const float* b1  = (const float*)d_in[2];
    const float* g1  = (const float*)d_in[3];
    const float* be1 = (const float*)d_in[4];
    const float* W2  = (const float*)d_in[5];
    const float* b2  = (const float*)d_in[6];
    const float* g2  = (const float*)d_in[7];
    const float* be2 = (const float*)d_in[8];
    const float* W3  = (const float*)d_in[9];
    const float* b3  = (const float*)d_in[10];
    const float* g3  = (const float*)d_in[11];
    const float* be3 = (const float*)d_in[12];
    const float* W4  = (const float*)d_in[13];
    const float* b4  = (const float*)d_in[14];
    const float* g4  = (const float*)d_in[15];
    const float* be4 = (const float*)d_in[16];
    float* out = (float*)d_out;

    const int smem_bytes = (2 * BT * SSTR + KC * HID_D + 3 * HID_D) * (int)sizeof(float);
    cudaFuncSetAttribute(mlp_fused_kernel,
                         cudaFuncAttributeMaxDynamicSharedMemorySize, smem_bytes);

    dim3 grid(NBATCH / BT, NPOL);   // 64 x 64 = 4096 CTAs
    mlp_fused_kernel<<<grid, NTHREADS, smem_bytes>>>(
        obs,
        W1, b1, g1, be1,
        W2, b2, g2, be2,
        W3, b3, g3, be3,
        W4, b4, g4, be4,
        out);
}